// round 14
// baseline (speedup 1.0000x reference)
#include <cuda_runtime.h>

#define NIMG 8
#define IMG  512
#define NPIX (IMG * IMG)

__device__ float g_min_a[NIMG * NPIX];
__device__ float g_min_b[NIMG * NPIX];
__device__ float g_max_a[NIMG * NPIX];
__device__ float g_max_b[NIMG * NPIX];

template <bool M> __device__ __forceinline__ float xop(float a, float b) {
    return M ? fminf(a, b) : fmaxf(a, b);
}
__device__ __forceinline__ float fmin3(float a, float b, float c) { return fminf(a, fminf(b, c)); }
__device__ __forceinline__ float fmax3(float a, float b, float c) { return fmaxf(a, fmaxf(b, c)); }

__device__ __forceinline__ unsigned long long pk2(float lo, float hi) {
    unsigned long long r;
    asm("mov.b64 %0, {%1, %2};" : "=l"(r) : "f"(lo), "f"(hi));
    return r;
}
__device__ __forceinline__ void upk2(unsigned long long v, float& lo, float& hi) {
    asm("mov.b64 {%0, %1}, %2;" : "=f"(lo), "=f"(hi) : "l"(v));
}
__device__ __forceinline__ unsigned long long fma2(unsigned long long a, unsigned long long b,
                                                   unsigned long long c) {
    unsigned long long d;
    asm("fma.rn.f32x2 %0, %1, %2, %3;" : "=l"(d) : "l"(a), "l"(b), "l"(c));
    return d;
}

// ---- round: fused 4 iterations, 2 cols x 24 rows/thread, 256 thr, 16 out ---
template <bool M>
__device__ __forceinline__ void do_round(const float* __restrict__ s, float* __restrict__ dp,
                                         float (*eL)[8][24], float (*eR)[8][24]) {
    const int tid = threadIdx.x;
    const int warp = tid >> 5, lane = tid & 31;
    const int tile = blockIdx.x;
    const int r0 = tile * 16 - 4;
    const int col = warp * 64 + lane * 2;
    const float BND = M ? __int_as_float(0x7F800000) : __int_as_float(0xFF800000);

    float2 d[24];
#pragma unroll
    for (int i = 0; i < 24; i++) {
        int rr = r0 + i;
        if (rr >= 0 && rr < IMG) d[i] = *(const float2*)(s + (size_t)rr * IMG + col);
        else                     d[i] = make_float2(BND, BND);
    }

#pragma unroll
    for (int it = 0; it < 4; it++) {
        const int p = it & 1;
        if (lane == 0) {
#pragma unroll
            for (int i = 0; i < 24; i++) eL[p][warp][i] = d[i].x;
        } else if (lane == 31) {
#pragma unroll
            for (int i = 0; i < 24; i++) eR[p][warp][i] = d[i].y;
        }
        __syncthreads();

        const int lo = it + 1, hi = 22 - it;
        float2 hp, hc;
        {
            float2 v = d[lo - 1];
            float L = __shfl_up_sync(0xffffffffu, v.y, 1);
            float R = __shfl_down_sync(0xffffffffu, v.x, 1);
            if (lane == 0)  L = (warp == 0) ? BND : eR[p][warp - 1][lo - 1];
            if (lane == 31) R = (warp == 7) ? BND : eL[p][warp + 1][lo - 1];
            float m = xop<M>(v.x, v.y);
            hp.x = xop<M>(L, m); hp.y = xop<M>(m, R);
            v = d[lo];
            L = __shfl_up_sync(0xffffffffu, v.y, 1);
            R = __shfl_down_sync(0xffffffffu, v.x, 1);
            if (lane == 0)  L = (warp == 0) ? BND : eR[p][warp - 1][lo];
            if (lane == 31) R = (warp == 7) ? BND : eL[p][warp + 1][lo];
            m = xop<M>(v.x, v.y);
            hc.x = xop<M>(L, m); hc.y = xop<M>(m, R);
        }
#pragma unroll
        for (int r = lo; r <= hi; r++) {
            float2 v = d[r + 1];
            float L = __shfl_up_sync(0xffffffffu, v.y, 1);
            float R = __shfl_down_sync(0xffffffffu, v.x, 1);
            if (lane == 0)  L = (warp == 0) ? BND : eR[p][warp - 1][r + 1];
            if (lane == 31) R = (warp == 7) ? BND : eL[p][warp + 1][r + 1];
            float m = xop<M>(v.x, v.y);
            float2 hn;
            hn.x = xop<M>(L, m); hn.y = xop<M>(m, R);

            if (M) {
                d[r].x += fmin3(hp.x, hc.x, hn.x);
                d[r].y += fmin3(hp.y, hc.y, hn.y);
            } else {
                d[r].x += fmax3(hp.x, hc.x, hn.x);
                d[r].y += fmax3(hp.y, hc.y, hn.y);
            }
            hp = hc; hc = hn;
        }
    }

#pragma unroll
    for (int i = 4; i < 20; i++) {
        int rr = r0 + i;   // tile*16 .. tile*16+15, always in range
        *(float2*)(dp + (size_t)rr * IMG + col) = d[i];
    }
}

__global__ __launch_bounds__(256, 3) void round_kernel(const float* __restrict__ srcMin,
                                                       const float* __restrict__ srcMax,
                                                       float* __restrict__ dstMin,
                                                       float* __restrict__ dstMax) {
    __shared__ float eL[2][8][24];
    __shared__ float eR[2][8][24];
    const size_t ib = (size_t)blockIdx.y * NPIX;
    if (blockIdx.z == 0) do_round<true>(srcMin + ib, dstMin + ib, eL, eR);
    else                 do_round<false>(srcMax + ib, dstMax + ib, eL, eR);
}

// ---- merged head + border, self-folding weights, race-free writes ----------
// grid (272, 1, NIMG): blockIdx.x < 256 -> interior head tile (masked writes),
//                      blockIdx.x >= 256 -> border ring pixels (exclusive owner).
__global__ __launch_bounds__(128) void head_kernel(const float* __restrict__ gmin,
                                                   const float* __restrict__ gmax,
                                                   const float* __restrict__ w0,
                                                   const float* __restrict__ b0,
                                                   const float* __restrict__ w1,
                                                   const float* __restrict__ b1,
                                                   const float* __restrict__ w2,
                                                   const float* __restrict__ b2,
                                                   float* __restrict__ out) {
    __shared__ float Amin[32][9], Amax[32][9], Bs[32][9];
    __shared__ unsigned long long A2s[32][18];
    __shared__ unsigned long long cb2s[32];
    __shared__ float w2s[32];
    __shared__ float b1s[32];

    const int tid = threadIdx.x;
    {
        float w0r[8], b0r[8];
#pragma unroll
        for (int c = 0; c < 8; c++) { w0r[c] = w0[c]; b0r[c] = 65536.f * b0[c]; }
        for (int id = tid; id < 288; id += 128) {
            int j = id / 9, t = id % 9;
            float amin = 0.f, amax = 0.f, bs = 0.f;
#pragma unroll
            for (int c = 0; c < 8; c++) {
                float w = w1[j * 72 + c * 9 + t];
                if (w0r[c] >= 0.f) amin += w * w0r[c]; else amax += w * w0r[c];
                bs += w * b0r[c];
            }
            Amin[j][t] = amin; Amax[j][t] = amax; Bs[j][t] = bs;
            A2s[j][t]     = pk2(amin, amin);
            A2s[j][9 + t] = pk2(amax, amax);
        }
        if (tid < 32) { w2s[tid] = w2[tid]; b1s[tid] = b1[tid]; }
        __syncthreads();
        if (tid < 32) {
            float cb = b1s[tid];
#pragma unroll
            for (int t = 0; t < 9; t++) cb += Bs[tid][t];
            cb2s[tid] = pk2(cb, cb);
        }
        __syncthreads();
    }

    const int img = blockIdx.z;
    const size_t ib = (size_t)img * NPIX;
    const float* gm = gmin + ib;
    const float* gx = gmax + ib;
    float* outp = out + ib;
    const float b2v = b2[0];

    if (blockIdx.x < 256) {
        const int tx = tid & 31, ty = tid >> 5;
        const int bx = blockIdx.x & 7, by = blockIdx.x >> 3;
        const int x0 = (bx * 32 + tx) * 2;
        const int y0 = (by * 4 + ty) * 4;
        const int xm2 = max(x0 - 2, 0);
        const int xp2 = min(x0 + 2, IMG - 2);

        unsigned long long tmin[6][3], tmax[6][3];
#pragma unroll
        for (int rr = 0; rr < 6; rr++) {
            int row = min(max(y0 + rr - 1, 0), IMG - 1);
            const float* pm = gm + (size_t)row * IMG;
            float2 L = *(const float2*)(pm + xm2);
            float2 Mv = *(const float2*)(pm + x0);
            float2 R = *(const float2*)(pm + xp2);
            tmin[rr][0] = pk2(L.y, Mv.x); tmin[rr][1] = pk2(Mv.x, Mv.y); tmin[rr][2] = pk2(Mv.y, R.x);
            const float* px = gx + (size_t)row * IMG;
            L = *(const float2*)(px + xm2);
            Mv = *(const float2*)(px + x0);
            R = *(const float2*)(px + xp2);
            tmax[rr][0] = pk2(L.y, Mv.x); tmax[rr][1] = pk2(Mv.x, Mv.y); tmax[rr][2] = pk2(Mv.y, R.x);
        }

        float accx[4] = {0.f, 0.f, 0.f, 0.f};
        float accy[4] = {0.f, 0.f, 0.f, 0.f};
#pragma unroll 2
        for (int j = 0; j < 32; j++) {
            unsigned long long u0 = cb2s[j], u1 = u0, u2 = u0, u3 = u0;
#pragma unroll
            for (int k = 0; k < 9; k++) {
                const int kh = k / 3, kw = k % 3;
                unsigned long long a = A2s[j][k];
                u0 = fma2(a, tmin[0 + kh][kw], u0);
                u1 = fma2(a, tmin[1 + kh][kw], u1);
                u2 = fma2(a, tmin[2 + kh][kw], u2);
                u3 = fma2(a, tmin[3 + kh][kw], u3);
            }
#pragma unroll
            for (int k = 0; k < 9; k++) {
                const int kh = k / 3, kw = k % 3;
                unsigned long long a = A2s[j][9 + k];
                u0 = fma2(a, tmax[0 + kh][kw], u0);
                u1 = fma2(a, tmax[1 + kh][kw], u1);
                u2 = fma2(a, tmax[2 + kh][kw], u2);
                u3 = fma2(a, tmax[3 + kh][kw], u3);
            }
            float w = w2s[j], lo, hi;
            upk2(u0, lo, hi);
            accx[0] = fmaf(w, fmaxf(lo, 0.f), accx[0]); accy[0] = fmaf(w, fmaxf(hi, 0.f), accy[0]);
            upk2(u1, lo, hi);
            accx[1] = fmaf(w, fmaxf(lo, 0.f), accx[1]); accy[1] = fmaf(w, fmaxf(hi, 0.f), accy[1]);
            upk2(u2, lo, hi);
            accx[2] = fmaf(w, fmaxf(lo, 0.f), accx[2]); accy[2] = fmaf(w, fmaxf(hi, 0.f), accy[2]);
            upk2(u3, lo, hi);
            accx[3] = fmaf(w, fmaxf(lo, 0.f), accx[3]); accy[3] = fmaf(w, fmaxf(hi, 0.f), accy[3]);
        }

#pragma unroll
        for (int i = 0; i < 4; i++) {
            int yy = y0 + i;
            if (yy == 0 || yy == IMG - 1) continue;
            float ox = b2v + accx[i];
            float oy = b2v + accy[i];
            if (x0 == 0)              outp[(size_t)yy * IMG + 1] = oy;
            else if (x0 == IMG - 2)   outp[(size_t)yy * IMG + (IMG - 2)] = ox;
            else                      *(float2*)(outp + (size_t)yy * IMG + x0) = make_float2(ox, oy);
        }
    } else {
        const int bi = (blockIdx.x - 256) * 128 + tid;
        if (bi >= 2044) return;
        int x, y;
        if (bi < 512)        { y = 0;   x = bi; }
        else if (bi < 1024)  { y = 511; x = bi - 512; }
        else if (bi < 1534)  { x = 0;   y = bi - 1024 + 1; }
        else                 { x = 511; y = bi - 1534 + 1; }

        float vmn[9], vmx[9];
        bool valid[9];
#pragma unroll
        for (int k = 0; k < 9; k++) {
            int ty = y + k / 3 - 1, tx = x + k % 3 - 1;
            valid[k] = (ty >= 0 && ty < IMG && tx >= 0 && tx < IMG);
            size_t off = (size_t)min(max(ty, 0), IMG - 1) * IMG + (size_t)min(max(tx, 0), IMG - 1);
            vmn[k] = valid[k] ? gm[off] : 0.f;
            vmx[k] = valid[k] ? gx[off] : 0.f;
        }
        float acc = 0.f;
        for (int j = 0; j < 32; j++) {
            float u = b1s[j];
#pragma unroll
            for (int k = 0; k < 9; k++) {
                if (valid[k])
                    u += Amin[j][k] * vmn[k] + Amax[j][k] * vmx[k] + Bs[j][k];
            }
            acc = fmaf(w2s[j], fmaxf(u, 0.f), acc);
        }
        outp[(size_t)y * IMG + x] = b2v + acc;
    }
}

// ---------------------------------------------------------------------------
extern "C" void kernel_launch(void* const* d_in, const int* in_sizes, int n_in,
                              void* d_out, int out_size) {
    const float* x  = (const float*)d_in[0];
    const float* w0 = (const float*)d_in[1];
    const float* b0 = (const float*)d_in[2];
    const float* w1 = (const float*)d_in[3];
    const float* b1 = (const float*)d_in[4];
    const float* w2 = (const float*)d_in[5];
    const float* b2 = (const float*)d_in[6];
    float* out = (float*)d_out;

    static float *pMinA = nullptr, *pMinB = nullptr, *pMaxA = nullptr, *pMaxB = nullptr;
    if (!pMinA) {
        cudaGetSymbolAddress((void**)&pMinA, g_min_a);
        cudaGetSymbolAddress((void**)&pMinB, g_min_b);
        cudaGetSymbolAddress((void**)&pMaxA, g_max_a);
        cudaGetSymbolAddress((void**)&pMaxB, g_max_b);
    }

    dim3 rblk(256);
    dim3 rgrd(IMG / 16, NIMG, 2);   // 16 out rows/CTA -> 512 CTAs
    round_kernel<<<rgrd, rblk>>>(x,     x,     pMinA, pMaxA);   // iters 1-4
    round_kernel<<<rgrd, rblk>>>(pMinA, pMaxA, pMinB, pMaxB);   // iters 5-8
    round_kernel<<<rgrd, rblk>>>(pMinB, pMaxB, pMinA, pMaxA);   // iters 9-12
    round_kernel<<<rgrd, rblk>>>(pMinA, pMaxA, pMinB, pMaxB);   // iters 13-16

    dim3 hgrd(272, 1, NIMG);
    head_kernel<<<hgrd, dim3(128)>>>(pMinB, pMaxB, w0, b0, w1, b1, w2, b2, out);
}

// round 15
// speedup vs baseline: 1.0732x; 1.0732x over previous
#include <cuda_runtime.h>

#define NIMG 8
#define IMG  512
#define NPIX (IMG * IMG)
#define NCTA 512ULL

__device__ float g_min_a[NIMG * NPIX];
__device__ float g_min_b[NIMG * NPIX];
__device__ float g_max_a[NIMG * NPIX];
__device__ float g_max_b[NIMG * NPIX];
__device__ unsigned long long g_bar;   // monotonic barrier counter (never reset)

__device__ __forceinline__ float fmin3(float a, float b, float c) { return fminf(a, fminf(b, c)); }
__device__ __forceinline__ float fmax3(float a, float b, float c) { return fmaxf(a, fmaxf(b, c)); }

__device__ __forceinline__ unsigned long long pk2(float lo, float hi) {
    unsigned long long r;
    asm("mov.b64 %0, {%1, %2};" : "=l"(r) : "f"(lo), "f"(hi));
    return r;
}
__device__ __forceinline__ void upk2(unsigned long long v, float& lo, float& hi) {
    asm("mov.b64 {%0, %1}, %2;" : "=f"(lo), "=f"(hi) : "l"(v));
}
__device__ __forceinline__ unsigned long long fma2(unsigned long long a, unsigned long long b,
                                                   unsigned long long c) {
    unsigned long long d;
    asm("fma.rn.f32x2 %0, %1, %2, %3;" : "=l"(d) : "l"(a), "l"(b), "l"(c));
    return d;
}

// Resident-grid barrier: all NCTA CTAs are co-resident by construction
// (__launch_bounds__(128,4) -> >=592 slots >= 512 CTAs). Monotonic counter.
__device__ __forceinline__ void grid_barrier(int tid) {
    __threadfence();
    __syncthreads();
    if (tid == 0) {
        unsigned long long old = atomicAdd(&g_bar, 1ULL);
        unsigned long long target = (old / NCTA + 1ULL) * NCTA;
        while (atomicAdd(&g_bar, 0ULL) < target) __nanosleep(64);
    }
    __syncthreads();
}

// ---- 4 fused pooling iterations on a 16-row register trapezoid (R4-proven) -
template <bool M>
__device__ __forceinline__ float4 hpool16(float4 v, int r, int p, int warp, int lane,
                                          const float* eL, const float* eR, float BND) {
    float left  = __shfl_up_sync(0xffffffffu, v.w, 1);
    float right = __shfl_down_sync(0xffffffffu, v.x, 1);
    if (lane == 0)  left  = (warp == 0) ? BND : eR[((p * 4) + warp - 1) * 16 + r];
    if (lane == 31) right = (warp == 3) ? BND : eL[((p * 4) + warp + 1) * 16 + r];
    float4 h;
    if (M) {
        h.x = fmin3(left, v.x, v.y); h.y = fmin3(v.x, v.y, v.z);
        h.z = fmin3(v.y, v.z, v.w);  h.w = fmin3(v.z, v.w, right);
    } else {
        h.x = fmax3(left, v.x, v.y); h.y = fmax3(v.x, v.y, v.z);
        h.z = fmax3(v.y, v.z, v.w);  h.w = fmax3(v.z, v.w, right);
    }
    return h;
}

template <bool M>
__device__ __forceinline__ void iters4(float4 (&d)[16], float* eL, float* eR,
                                       int warp, int lane, float BND) {
#pragma unroll
    for (int it = 0; it < 4; it++) {
        const int p = it & 1;
        if (lane == 0) {
#pragma unroll
            for (int i = 0; i < 16; i++) eL[((p * 4) + warp) * 16 + i] = d[i].x;
        } else if (lane == 31) {
#pragma unroll
            for (int i = 0; i < 16; i++) eR[((p * 4) + warp) * 16 + i] = d[i].w;
        }
        __syncthreads();

        const int lo = it + 1, hi = 14 - it;
        float4 hp = hpool16<M>(d[lo - 1], lo - 1, p, warp, lane, eL, eR, BND);
        float4 hc = hpool16<M>(d[lo],     lo,     p, warp, lane, eL, eR, BND);
#pragma unroll
        for (int r = lo; r <= hi; r++) {
            float4 hn = hpool16<M>(d[r + 1], r + 1, p, warp, lane, eL, eR, BND);
            if (M) {
                d[r].x += fmin3(hp.x, hc.x, hn.x); d[r].y += fmin3(hp.y, hc.y, hn.y);
                d[r].z += fmin3(hp.z, hc.z, hn.z); d[r].w += fmin3(hp.w, hc.w, hn.w);
            } else {
                d[r].x += fmax3(hp.x, hc.x, hn.x); d[r].y += fmax3(hp.y, hc.y, hn.y);
                d[r].z += fmax3(hp.z, hc.z, hn.z); d[r].w += fmax3(hp.w, hc.w, hn.w);
            }
            hp = hc; hc = hn;
        }
        // next iteration overwrites the other smem bank; syncthreads at top of
        // next it (via edge-write + __syncthreads) orders reuse
    }
}

// ---- persistent round pipeline: 4 rounds, 3 grid barriers, halo reloads ----
template <bool M>
__device__ void run_field(const float* __restrict__ xs, float* __restrict__ bA,
                          float* __restrict__ bB, float* eL, float* eR) {
    const int tid = threadIdx.x;
    const int warp = tid >> 5, lane = tid & 31;
    const int tile = blockIdx.x;
    const int r0 = tile * 8 - 4;
    const int col = warp * 128 + lane * 4;
    const float BND = M ? __int_as_float(0x7F800000) : __int_as_float(0xFF800000);

    float4 d[16];
    // ---- round 1: full load from x ----
#pragma unroll
    for (int i = 0; i < 16; i++) {
        int rr = r0 + i;
        if (rr >= 0 && rr < IMG) d[i] = *(const float4*)(xs + (size_t)rr * IMG + col);
        else                     d[i] = make_float4(BND, BND, BND, BND);
    }
    iters4<M>(d, eL, eR, warp, lane, BND);
#pragma unroll
    for (int i = 4; i < 12; i++)
        *(float4*)(bA + (size_t)(r0 + i) * IMG + col) = d[i];

    // ---- rounds 2..4: interior persists in registers; reload halo only ----
#pragma unroll 1
    for (int rnd = 1; rnd < 4; rnd++) {
        grid_barrier(tid);
        const float* hsrc = (rnd == 2) ? bB : bA;   // previous round's dst
        float* dst        = (rnd == 2) ? bA : bB;   // alternate: A,B,A,B
#pragma unroll
        for (int i = 0; i < 4; i++) {
            int rr = r0 + i;
            d[i] = (rr >= 0) ? *(const float4*)(hsrc + (size_t)rr * IMG + col)
                             : make_float4(BND, BND, BND, BND);
            int rr2 = r0 + 12 + i;
            d[12 + i] = (rr2 < IMG) ? *(const float4*)(hsrc + (size_t)rr2 * IMG + col)
                                    : make_float4(BND, BND, BND, BND);
        }
        iters4<M>(d, eL, eR, warp, lane, BND);
#pragma unroll
        for (int i = 4; i < 12; i++)
            *(float4*)(dst + (size_t)(r0 + i) * IMG + col) = d[i];
    }
}

__global__ __launch_bounds__(128, 4) void persist_kernel(const float* __restrict__ x,
                                                         float* __restrict__ minA,
                                                         float* __restrict__ minB,
                                                         float* __restrict__ maxA,
                                                         float* __restrict__ maxB,
                                                         int imgbase) {
    __shared__ float eL[2 * 4 * 16];
    __shared__ float eR[2 * 4 * 16];
    const int img = imgbase + blockIdx.y;
    const size_t ib = (size_t)img * NPIX;
    if (blockIdx.z == 0) run_field<true>(x + ib, minA + ib, minB + ib, eL, eR);
    else                 run_field<false>(x + ib, maxA + ib, maxB + ib, eL, eR);
}

// ---- merged head + border (byte-identical to the 94.7us winner) ------------
__global__ __launch_bounds__(128) void head_kernel(const float* __restrict__ gmin,
                                                   const float* __restrict__ gmax,
                                                   const float* __restrict__ w0,
                                                   const float* __restrict__ b0,
                                                   const float* __restrict__ w1,
                                                   const float* __restrict__ b1,
                                                   const float* __restrict__ w2,
                                                   const float* __restrict__ b2,
                                                   float* __restrict__ out) {
    __shared__ float Amin[32][9], Amax[32][9], Bs[32][9];
    __shared__ unsigned long long A2s[32][18];
    __shared__ unsigned long long cb2s[32];
    __shared__ float w2s[32];
    __shared__ float b1s[32];

    const int tid = threadIdx.x;
    {
        float w0r[8], b0r[8];
#pragma unroll
        for (int c = 0; c < 8; c++) { w0r[c] = w0[c]; b0r[c] = 65536.f * b0[c]; }
        for (int id = tid; id < 288; id += 128) {
            int j = id / 9, t = id % 9;
            float amin = 0.f, amax = 0.f, bs = 0.f;
#pragma unroll
            for (int c = 0; c < 8; c++) {
                float w = w1[j * 72 + c * 9 + t];
                if (w0r[c] >= 0.f) amin += w * w0r[c]; else amax += w * w0r[c];
                bs += w * b0r[c];
            }
            Amin[j][t] = amin; Amax[j][t] = amax; Bs[j][t] = bs;
            A2s[j][t]     = pk2(amin, amin);
            A2s[j][9 + t] = pk2(amax, amax);
        }
        if (tid < 32) { w2s[tid] = w2[tid]; b1s[tid] = b1[tid]; }
        __syncthreads();
        if (tid < 32) {
            float cb = b1s[tid];
#pragma unroll
            for (int t = 0; t < 9; t++) cb += Bs[tid][t];
            cb2s[tid] = pk2(cb, cb);
        }
        __syncthreads();
    }

    const int img = blockIdx.z;
    const size_t ib = (size_t)img * NPIX;
    const float* gm = gmin + ib;
    const float* gx = gmax + ib;
    float* outp = out + ib;
    const float b2v = b2[0];

    if (blockIdx.x < 256) {
        const int tx = tid & 31, ty = tid >> 5;
        const int bx = blockIdx.x & 7, by = blockIdx.x >> 3;
        const int x0 = (bx * 32 + tx) * 2;
        const int y0 = (by * 4 + ty) * 4;
        const int xm2 = max(x0 - 2, 0);
        const int xp2 = min(x0 + 2, IMG - 2);

        unsigned long long tmin[6][3], tmax[6][3];
#pragma unroll
        for (int rr = 0; rr < 6; rr++) {
            int row = min(max(y0 + rr - 1, 0), IMG - 1);
            const float* pm = gm + (size_t)row * IMG;
            float2 L = *(const float2*)(pm + xm2);
            float2 Mv = *(const float2*)(pm + x0);
            float2 R = *(const float2*)(pm + xp2);
            tmin[rr][0] = pk2(L.y, Mv.x); tmin[rr][1] = pk2(Mv.x, Mv.y); tmin[rr][2] = pk2(Mv.y, R.x);
            const float* px = gx + (size_t)row * IMG;
            L = *(const float2*)(px + xm2);
            Mv = *(const float2*)(px + x0);
            R = *(const float2*)(px + xp2);
            tmax[rr][0] = pk2(L.y, Mv.x); tmax[rr][1] = pk2(Mv.x, Mv.y); tmax[rr][2] = pk2(Mv.y, R.x);
        }

        float accx[4] = {0.f, 0.f, 0.f, 0.f};
        float accy[4] = {0.f, 0.f, 0.f, 0.f};
#pragma unroll 2
        for (int j = 0; j < 32; j++) {
            unsigned long long u0 = cb2s[j], u1 = u0, u2 = u0, u3 = u0;
#pragma unroll
            for (int k = 0; k < 9; k++) {
                const int kh = k / 3, kw = k % 3;
                unsigned long long a = A2s[j][k];
                u0 = fma2(a, tmin[0 + kh][kw], u0);
                u1 = fma2(a, tmin[1 + kh][kw], u1);
                u2 = fma2(a, tmin[2 + kh][kw], u2);
                u3 = fma2(a, tmin[3 + kh][kw], u3);
            }
#pragma unroll
            for (int k = 0; k < 9; k++) {
                const int kh = k / 3, kw = k % 3;
                unsigned long long a = A2s[j][9 + k];
                u0 = fma2(a, tmax[0 + kh][kw], u0);
                u1 = fma2(a, tmax[1 + kh][kw], u1);
                u2 = fma2(a, tmax[2 + kh][kw], u2);
                u3 = fma2(a, tmax[3 + kh][kw], u3);
            }
            float w = w2s[j], lo, hi;
            upk2(u0, lo, hi);
            accx[0] = fmaf(w, fmaxf(lo, 0.f), accx[0]); accy[0] = fmaf(w, fmaxf(hi, 0.f), accy[0]);
            upk2(u1, lo, hi);
            accx[1] = fmaf(w, fmaxf(lo, 0.f), accx[1]); accy[1] = fmaf(w, fmaxf(hi, 0.f), accy[1]);
            upk2(u2, lo, hi);
            accx[2] = fmaf(w, fmaxf(lo, 0.f), accx[2]); accy[2] = fmaf(w, fmaxf(hi, 0.f), accy[2]);
            upk2(u3, lo, hi);
            accx[3] = fmaf(w, fmaxf(lo, 0.f), accx[3]); accy[3] = fmaf(w, fmaxf(hi, 0.f), accy[3]);
        }

#pragma unroll
        for (int i = 0; i < 4; i++) {
            int yy = y0 + i;
            if (yy == 0 || yy == IMG - 1) continue;
            float ox = b2v + accx[i];
            float oy = b2v + accy[i];
            if (x0 == 0)              outp[(size_t)yy * IMG + 1] = oy;
            else if (x0 == IMG - 2)   outp[(size_t)yy * IMG + (IMG - 2)] = ox;
            else                      *(float2*)(outp + (size_t)yy * IMG + x0) = make_float2(ox, oy);
        }
    } else {
        const int bi = (blockIdx.x - 256) * 128 + tid;
        if (bi >= 2044) return;
        int x, y;
        if (bi < 512)        { y = 0;   x = bi; }
        else if (bi < 1024)  { y = 511; x = bi - 512; }
        else if (bi < 1534)  { x = 0;   y = bi - 1024 + 1; }
        else                 { x = 511; y = bi - 1534 + 1; }

        float vmn[9], vmx[9];
        bool valid[9];
#pragma unroll
        for (int k = 0; k < 9; k++) {
            int ty = y + k / 3 - 1, tx = x + k % 3 - 1;
            valid[k] = (ty >= 0 && ty < IMG && tx >= 0 && tx < IMG);
            size_t off = (size_t)min(max(ty, 0), IMG - 1) * IMG + (size_t)min(max(tx, 0), IMG - 1);
            vmn[k] = valid[k] ? gm[off] : 0.f;
            vmx[k] = valid[k] ? gx[off] : 0.f;
        }
        float acc = 0.f;
        for (int j = 0; j < 32; j++) {
            float u = b1s[j];
#pragma unroll
            for (int k = 0; k < 9; k++) {
                if (valid[k])
                    u += Amin[j][k] * vmn[k] + Amax[j][k] * vmx[k] + Bs[j][k];
            }
            acc = fmaf(w2s[j], fmaxf(u, 0.f), acc);
        }
        outp[(size_t)y * IMG + x] = b2v + acc;
    }
}

// ---------------------------------------------------------------------------
extern "C" void kernel_launch(void* const* d_in, const int* in_sizes, int n_in,
                              void* d_out, int out_size) {
    const float* x  = (const float*)d_in[0];
    const float* w0 = (const float*)d_in[1];
    const float* b0 = (const float*)d_in[2];
    const float* w1 = (const float*)d_in[3];
    const float* b1 = (const float*)d_in[4];
    const float* w2 = (const float*)d_in[5];
    const float* b2 = (const float*)d_in[6];
    float* out = (float*)d_out;

    static float *pMinA = nullptr, *pMinB = nullptr, *pMaxA = nullptr, *pMaxB = nullptr;
    if (!pMinA) {
        cudaGetSymbolAddress((void**)&pMinA, g_min_a);
        cudaGetSymbolAddress((void**)&pMinB, g_min_b);
        cudaGetSymbolAddress((void**)&pMaxA, g_max_a);
        cudaGetSymbolAddress((void**)&pMaxB, g_max_b);
    }

    // Two persistent launches (4 images each, 512 CTAs: guaranteed resident),
    // each runs all 16 pooling iterations with 3 internal grid barriers.
    dim3 pgrd(64, 4, 2);
    persist_kernel<<<pgrd, 128>>>(x, pMinA, pMinB, pMaxA, pMaxB, 0);
    persist_kernel<<<pgrd, 128>>>(x, pMinA, pMinB, pMaxA, pMaxB, 4);

    dim3 hgrd(272, 1, NIMG);
    head_kernel<<<hgrd, 128>>>(pMinB, pMaxB, w0, b0, w1, b1, w2, b2, out);
}

// round 16
// speedup vs baseline: 1.1403x; 1.0625x over previous
#include <cuda_runtime.h>

#define NIMG 8
#define IMG  512
#define NPIX (IMG * IMG)

__device__ float g_min_a[NIMG * NPIX];
__device__ float g_min_b[NIMG * NPIX];
__device__ float g_max_a[NIMG * NPIX];
__device__ float g_max_b[NIMG * NPIX];

__device__ __forceinline__ float fmin3(float a, float b, float c) { return fminf(a, fminf(b, c)); }
__device__ __forceinline__ float fmax3(float a, float b, float c) { return fmaxf(a, fmaxf(b, c)); }

__device__ __forceinline__ unsigned long long pk2(float lo, float hi) {
    unsigned long long r;
    asm("mov.b64 %0, {%1, %2};" : "=l"(r) : "f"(lo), "f"(hi));
    return r;
}
__device__ __forceinline__ void upk2(unsigned long long v, float& lo, float& hi) {
    asm("mov.b64 {%0, %1}, %2;" : "=f"(lo), "=f"(hi) : "l"(v));
}
__device__ __forceinline__ unsigned long long fma2(unsigned long long a, unsigned long long b,
                                                   unsigned long long c) {
    unsigned long long d;
    asm("fma.rn.f32x2 %0, %1, %2, %3;" : "=l"(d) : "l"(a), "l"(b), "l"(c));
    return d;
}

// ---- round: R13-proven fused 4 iterations, 16 rows x 4 cols/thread ---------
template <bool M>
__device__ __forceinline__ float4 hpool16(float4 v, int r, int p, int warp, int lane,
                                          const float* eL, const float* eR, float BND) {
    float left  = __shfl_up_sync(0xffffffffu, v.w, 1);
    float right = __shfl_down_sync(0xffffffffu, v.x, 1);
    if (lane == 0)  left  = (warp == 0) ? BND : eR[((p * 4) + warp - 1) * 16 + r];
    if (lane == 31) right = (warp == 3) ? BND : eL[((p * 4) + warp + 1) * 16 + r];
    float4 h;
    if (M) {
        h.x = fmin3(left, v.x, v.y); h.y = fmin3(v.x, v.y, v.z);
        h.z = fmin3(v.y, v.z, v.w);  h.w = fmin3(v.z, v.w, right);
    } else {
        h.x = fmax3(left, v.x, v.y); h.y = fmax3(v.x, v.y, v.z);
        h.z = fmax3(v.y, v.z, v.w);  h.w = fmax3(v.z, v.w, right);
    }
    return h;
}

template <bool M>
__device__ __forceinline__ void do_round(const float* __restrict__ s, float* __restrict__ dp,
                                         float* eL, float* eR) {
    const int tid = threadIdx.x;
    const int warp = tid >> 5, lane = tid & 31;
    const int tile = blockIdx.x;
    const int r0 = tile * 8 - 4;
    const int col = warp * 128 + lane * 4;
    const float BND = M ? __int_as_float(0x7F800000) : __int_as_float(0xFF800000);

    float4 d[16];
#pragma unroll
    for (int i = 0; i < 16; i++) {
        int rr = r0 + i;
        if (rr >= 0 && rr < IMG) d[i] = *(const float4*)(s + (size_t)rr * IMG + col);
        else                     d[i] = make_float4(BND, BND, BND, BND);
    }

#pragma unroll
    for (int it = 0; it < 4; it++) {
        const int p = it & 1;
        if (lane == 0) {
#pragma unroll
            for (int i = 0; i < 16; i++) eL[((p * 4) + warp) * 16 + i] = d[i].x;
        } else if (lane == 31) {
#pragma unroll
            for (int i = 0; i < 16; i++) eR[((p * 4) + warp) * 16 + i] = d[i].w;
        }
        __syncthreads();

        const int lo = it + 1, hi = 14 - it;
        float4 hp = hpool16<M>(d[lo - 1], lo - 1, p, warp, lane, eL, eR, BND);
        float4 hc = hpool16<M>(d[lo],     lo,     p, warp, lane, eL, eR, BND);
#pragma unroll
        for (int r = lo; r <= hi; r++) {
            float4 hn = hpool16<M>(d[r + 1], r + 1, p, warp, lane, eL, eR, BND);
            if (M) {
                d[r].x += fmin3(hp.x, hc.x, hn.x); d[r].y += fmin3(hp.y, hc.y, hn.y);
                d[r].z += fmin3(hp.z, hc.z, hn.z); d[r].w += fmin3(hp.w, hc.w, hn.w);
            } else {
                d[r].x += fmax3(hp.x, hc.x, hn.x); d[r].y += fmax3(hp.y, hc.y, hn.y);
                d[r].z += fmax3(hp.z, hc.z, hn.z); d[r].w += fmax3(hp.w, hc.w, hn.w);
            }
            hp = hc; hc = hn;
        }
    }

#pragma unroll
    for (int i = 4; i < 12; i++) {
        int rr = r0 + i;
        *(float4*)(dp + (size_t)rr * IMG + col) = d[i];
    }
}

__global__ __launch_bounds__(128, 6) void round_kernel(const float* __restrict__ srcMin,
                                                       const float* __restrict__ srcMax,
                                                       float* __restrict__ dstMin,
                                                       float* __restrict__ dstMax) {
    __shared__ float eL[2 * 4 * 16];
    __shared__ float eR[2 * 4 * 16];
    const size_t ib = (size_t)blockIdx.y * NPIX;
    if (blockIdx.z == 0) do_round<true>(srcMin + ib, dstMin + ib, eL, eR);
    else                 do_round<false>(srcMax + ib, dstMax + ib, eL, eR);
}

// ---- merged head + border, self-folding weights, packed epilogue -----------
__global__ __launch_bounds__(128) void head_kernel(const float* __restrict__ gmin,
                                                   const float* __restrict__ gmax,
                                                   const float* __restrict__ w0,
                                                   const float* __restrict__ b0,
                                                   const float* __restrict__ w1,
                                                   const float* __restrict__ b1,
                                                   const float* __restrict__ w2,
                                                   const float* __restrict__ b2,
                                                   float* __restrict__ out) {
    __shared__ float Amin[32][9], Amax[32][9], Bs[32][9];
    __shared__ unsigned long long A2s[32][18];
    __shared__ unsigned long long cb2s[32];
    __shared__ unsigned long long w2p[32];
    __shared__ float w2s[32];
    __shared__ float b1s[32];

    const int tid = threadIdx.x;
    {
        float w0r[8], b0r[8];
#pragma unroll
        for (int c = 0; c < 8; c++) { w0r[c] = w0[c]; b0r[c] = 65536.f * b0[c]; }
        for (int id = tid; id < 288; id += 128) {
            int j = id / 9, t = id % 9;
            float amin = 0.f, amax = 0.f, bs = 0.f;
#pragma unroll
            for (int c = 0; c < 8; c++) {
                float w = w1[j * 72 + c * 9 + t];
                if (w0r[c] >= 0.f) amin += w * w0r[c]; else amax += w * w0r[c];
                bs += w * b0r[c];
            }
            Amin[j][t] = amin; Amax[j][t] = amax; Bs[j][t] = bs;
            A2s[j][t]     = pk2(amin, amin);
            A2s[j][9 + t] = pk2(amax, amax);
        }
        if (tid < 32) {
            float wv = w2[tid];
            w2s[tid] = wv;
            w2p[tid] = pk2(wv, wv);
            b1s[tid] = b1[tid];
        }
        __syncthreads();
        if (tid < 32) {
            float cb = b1s[tid];
#pragma unroll
            for (int t = 0; t < 9; t++) cb += Bs[tid][t];
            cb2s[tid] = pk2(cb, cb);
        }
        __syncthreads();
    }

    const int img = blockIdx.z;
    const size_t ib = (size_t)img * NPIX;
    const float* gm = gmin + ib;
    const float* gx = gmax + ib;
    float* outp = out + ib;
    const float b2v = b2[0];

    if (blockIdx.x < 256) {
        const int tx = tid & 31, ty = tid >> 5;
        const int bx = blockIdx.x & 7, by = blockIdx.x >> 3;
        const int x0 = (bx * 32 + tx) * 2;
        const int y0 = (by * 4 + ty) * 4;
        const int xm2 = max(x0 - 2, 0);
        const int xp2 = min(x0 + 2, IMG - 2);

        unsigned long long tmin[6][3], tmax[6][3];
#pragma unroll
        for (int rr = 0; rr < 6; rr++) {
            int row = min(max(y0 + rr - 1, 0), IMG - 1);
            const float* pm = gm + (size_t)row * IMG;
            float2 L = *(const float2*)(pm + xm2);
            float2 Mv = *(const float2*)(pm + x0);
            float2 R = *(const float2*)(pm + xp2);
            tmin[rr][0] = pk2(L.y, Mv.x); tmin[rr][1] = pk2(Mv.x, Mv.y); tmin[rr][2] = pk2(Mv.y, R.x);
            const float* px = gx + (size_t)row * IMG;
            L = *(const float2*)(px + xm2);
            Mv = *(const float2*)(px + x0);
            R = *(const float2*)(px + xp2);
            tmax[rr][0] = pk2(L.y, Mv.x); tmax[rr][1] = pk2(Mv.x, Mv.y); tmax[rr][2] = pk2(Mv.y, R.x);
        }

        unsigned long long accp[4] = {0ULL, 0ULL, 0ULL, 0ULL};
#pragma unroll 2
        for (int j = 0; j < 32; j++) {
            unsigned long long u0 = cb2s[j], u1 = u0, u2 = u0, u3 = u0;
#pragma unroll
            for (int k = 0; k < 9; k++) {
                const int kh = k / 3, kw = k % 3;
                unsigned long long a = A2s[j][k];
                u0 = fma2(a, tmin[0 + kh][kw], u0);
                u1 = fma2(a, tmin[1 + kh][kw], u1);
                u2 = fma2(a, tmin[2 + kh][kw], u2);
                u3 = fma2(a, tmin[3 + kh][kw], u3);
            }
#pragma unroll
            for (int k = 0; k < 9; k++) {
                const int kh = k / 3, kw = k % 3;
                unsigned long long a = A2s[j][9 + k];
                u0 = fma2(a, tmax[0 + kh][kw], u0);
                u1 = fma2(a, tmax[1 + kh][kw], u1);
                u2 = fma2(a, tmax[2 + kh][kw], u2);
                u3 = fma2(a, tmax[3 + kh][kw], u3);
            }
            unsigned long long wp = w2p[j];
            float lo, hi;
            upk2(u0, lo, hi);
            accp[0] = fma2(wp, pk2(fmaxf(lo, 0.f), fmaxf(hi, 0.f)), accp[0]);
            upk2(u1, lo, hi);
            accp[1] = fma2(wp, pk2(fmaxf(lo, 0.f), fmaxf(hi, 0.f)), accp[1]);
            upk2(u2, lo, hi);
            accp[2] = fma2(wp, pk2(fmaxf(lo, 0.f), fmaxf(hi, 0.f)), accp[2]);
            upk2(u3, lo, hi);
            accp[3] = fma2(wp, pk2(fmaxf(lo, 0.f), fmaxf(hi, 0.f)), accp[3]);
        }

#pragma unroll
        for (int i = 0; i < 4; i++) {
            int yy = y0 + i;
            if (yy == 0 || yy == IMG - 1) continue;
            float ax, ay;
            upk2(accp[i], ax, ay);
            float ox = b2v + ax;
            float oy = b2v + ay;
            if (x0 == 0)              outp[(size_t)yy * IMG + 1] = oy;
            else if (x0 == IMG - 2)   outp[(size_t)yy * IMG + (IMG - 2)] = ox;
            else                      *(float2*)(outp + (size_t)yy * IMG + x0) = make_float2(ox, oy);
        }
    } else {
        const int bi = (blockIdx.x - 256) * 128 + tid;
        if (bi >= 2044) return;
        int x, y;
        if (bi < 512)        { y = 0;   x = bi; }
        else if (bi < 1024)  { y = 511; x = bi - 512; }
        else if (bi < 1534)  { x = 0;   y = bi - 1024 + 1; }
        else                 { x = 511; y = bi - 1534 + 1; }

        float vmn[9], vmx[9];
        bool valid[9];
#pragma unroll
        for (int k = 0; k < 9; k++) {
            int ty = y + k / 3 - 1, tx = x + k % 3 - 1;
            valid[k] = (ty >= 0 && ty < IMG && tx >= 0 && tx < IMG);
            size_t off = (size_t)min(max(ty, 0), IMG - 1) * IMG + (size_t)min(max(tx, 0), IMG - 1);
            vmn[k] = valid[k] ? gm[off] : 0.f;
            vmx[k] = valid[k] ? gx[off] : 0.f;
        }
        float acc = 0.f;
        for (int j = 0; j < 32; j++) {
            float u = b1s[j];
#pragma unroll
            for (int k = 0; k < 9; k++) {
                if (valid[k])
                    u += Amin[j][k] * vmn[k] + Amax[j][k] * vmx[k] + Bs[j][k];
            }
            acc = fmaf(w2s[j], fmaxf(u, 0.f), acc);
        }
        outp[(size_t)y * IMG + x] = b2v + acc;
    }
}

// ---------------------------------------------------------------------------
extern "C" void kernel_launch(void* const* d_in, const int* in_sizes, int n_in,
                              void* d_out, int out_size) {
    const float* x  = (const float*)d_in[0];
    const float* w0 = (const float*)d_in[1];
    const float* b0 = (const float*)d_in[2];
    const float* w1 = (const float*)d_in[3];
    const float* b1 = (const float*)d_in[4];
    const float* w2 = (const float*)d_in[5];
    const float* b2 = (const float*)d_in[6];
    float* out = (float*)d_out;

    static float *pMinA = nullptr, *pMinB = nullptr, *pMaxA = nullptr, *pMaxB = nullptr;
    if (!pMinA) {
        cudaGetSymbolAddress((void**)&pMinA, g_min_a);
        cudaGetSymbolAddress((void**)&pMinB, g_min_b);
        cudaGetSymbolAddress((void**)&pMaxA, g_max_a);
        cudaGetSymbolAddress((void**)&pMaxB, g_max_b);
    }

    dim3 rblk(128);
    dim3 rgrd(IMG / 8, NIMG, 2);
    round_kernel<<<rgrd, rblk>>>(x,     x,     pMinA, pMaxA);   // iters 1-4
    round_kernel<<<rgrd, rblk>>>(pMinA, pMaxA, pMinB, pMaxB);   // iters 5-8
    round_kernel<<<rgrd, rblk>>>(pMinB, pMaxB, pMinA, pMaxA);   // iters 9-12
    round_kernel<<<rgrd, rblk>>>(pMinA, pMaxA, pMinB, pMaxB);   // iters 13-16

    dim3 hgrd(272, 1, NIMG);
    head_kernel<<<hgrd, 128>>>(pMinB, pMaxB, w0, b0, w1, b1, w2, b2, out);
}

// round 17
// speedup vs baseline: 1.1889x; 1.0426x over previous
#include <cuda_runtime.h>

#define NIMG 8
#define IMG  512
#define NPIX (IMG * IMG)

__device__ float g_min_a[NIMG * NPIX];
__device__ float g_min_b[NIMG * NPIX];
__device__ float g_max_a[NIMG * NPIX];
__device__ float g_max_b[NIMG * NPIX];

__device__ __forceinline__ float fmin3(float a, float b, float c) { return fminf(a, fminf(b, c)); }
__device__ __forceinline__ float fmax3(float a, float b, float c) { return fmaxf(a, fmaxf(b, c)); }

__device__ __forceinline__ unsigned long long pk2(float lo, float hi) {
    unsigned long long r;
    asm("mov.b64 %0, {%1, %2};" : "=l"(r) : "f"(lo), "f"(hi));
    return r;
}
__device__ __forceinline__ void upk2(unsigned long long v, float& lo, float& hi) {
    asm("mov.b64 {%0, %1}, %2;" : "=f"(lo), "=f"(hi) : "l"(v));
}
__device__ __forceinline__ unsigned long long fma2(unsigned long long a, unsigned long long b,
                                                   unsigned long long c) {
    unsigned long long d;
    asm("fma.rn.f32x2 %0, %1, %2, %3;" : "=l"(d) : "l"(a), "l"(b), "l"(c));
    return d;
}

// ---- round: R13-proven fused 4 iterations, 16 rows x 4 cols/thread ---------
template <bool M>
__device__ __forceinline__ float4 hpool16(float4 v, int r, int p, int warp, int lane,
                                          const float* eL, const float* eR, float BND) {
    float left  = __shfl_up_sync(0xffffffffu, v.w, 1);
    float right = __shfl_down_sync(0xffffffffu, v.x, 1);
    if (lane == 0)  left  = (warp == 0) ? BND : eR[((p * 4) + warp - 1) * 16 + r];
    if (lane == 31) right = (warp == 3) ? BND : eL[((p * 4) + warp + 1) * 16 + r];
    float4 h;
    if (M) {
        h.x = fmin3(left, v.x, v.y); h.y = fmin3(v.x, v.y, v.z);
        h.z = fmin3(v.y, v.z, v.w);  h.w = fmin3(v.z, v.w, right);
    } else {
        h.x = fmax3(left, v.x, v.y); h.y = fmax3(v.x, v.y, v.z);
        h.z = fmax3(v.y, v.z, v.w);  h.w = fmax3(v.z, v.w, right);
    }
    return h;
}

template <bool M>
__device__ __forceinline__ void do_round(const float* __restrict__ s, float* __restrict__ dp,
                                         float* eL, float* eR) {
    const int tid = threadIdx.x;
    const int warp = tid >> 5, lane = tid & 31;
    const int tile = blockIdx.x;
    const int r0 = tile * 8 - 4;
    const int col = warp * 128 + lane * 4;
    const float BND = M ? __int_as_float(0x7F800000) : __int_as_float(0xFF800000);

    float4 d[16];
#pragma unroll
    for (int i = 0; i < 16; i++) {
        int rr = r0 + i;
        if (rr >= 0 && rr < IMG) d[i] = *(const float4*)(s + (size_t)rr * IMG + col);
        else                     d[i] = make_float4(BND, BND, BND, BND);
    }

#pragma unroll
    for (int it = 0; it < 4; it++) {
        const int p = it & 1;
        if (lane == 0) {
#pragma unroll
            for (int i = 0; i < 16; i++) eL[((p * 4) + warp) * 16 + i] = d[i].x;
        } else if (lane == 31) {
#pragma unroll
            for (int i = 0; i < 16; i++) eR[((p * 4) + warp) * 16 + i] = d[i].w;
        }
        __syncthreads();

        const int lo = it + 1, hi = 14 - it;
        float4 hp = hpool16<M>(d[lo - 1], lo - 1, p, warp, lane, eL, eR, BND);
        float4 hc = hpool16<M>(d[lo],     lo,     p, warp, lane, eL, eR, BND);
#pragma unroll
        for (int r = lo; r <= hi; r++) {
            float4 hn = hpool16<M>(d[r + 1], r + 1, p, warp, lane, eL, eR, BND);
            if (M) {
                d[r].x += fmin3(hp.x, hc.x, hn.x); d[r].y += fmin3(hp.y, hc.y, hn.y);
                d[r].z += fmin3(hp.z, hc.z, hn.z); d[r].w += fmin3(hp.w, hc.w, hn.w);
            } else {
                d[r].x += fmax3(hp.x, hc.x, hn.x); d[r].y += fmax3(hp.y, hc.y, hn.y);
                d[r].z += fmax3(hp.z, hc.z, hn.z); d[r].w += fmax3(hp.w, hc.w, hn.w);
            }
            hp = hc; hc = hn;
        }
    }

#pragma unroll
    for (int i = 4; i < 12; i++) {
        int rr = r0 + i;
        *(float4*)(dp + (size_t)rr * IMG + col) = d[i];
    }
}

__global__ __launch_bounds__(128) void round_kernel(const float* __restrict__ srcMin,
                                                    const float* __restrict__ srcMax,
                                                    float* __restrict__ dstMin,
                                                    float* __restrict__ dstMax) {
    __shared__ float eL[2 * 4 * 16];
    __shared__ float eR[2 * 4 * 16];
    const size_t ib = (size_t)blockIdx.y * NPIX;
    if (blockIdx.z == 0) do_round<true>(srcMin + ib, dstMin + ib, eL, eR);
    else                 do_round<false>(srcMax + ib, dstMax + ib, eL, eR);
}

// ---- merged head + border, self-folding weights, packed epilogue -----------
__global__ __launch_bounds__(128) void head_kernel(const float* __restrict__ gmin,
                                                   const float* __restrict__ gmax,
                                                   const float* __restrict__ w0,
                                                   const float* __restrict__ b0,
                                                   const float* __restrict__ w1,
                                                   const float* __restrict__ b1,
                                                   const float* __restrict__ w2,
                                                   const float* __restrict__ b2,
                                                   float* __restrict__ out) {
    __shared__ float Amin[32][9], Amax[32][9], Bs[32][9];
    __shared__ unsigned long long A2s[32][18];
    __shared__ unsigned long long cb2s[32];
    __shared__ unsigned long long w2p[32];
    __shared__ float w2s[32];
    __shared__ float b1s[32];

    const int tid = threadIdx.x;
    {
        float w0r[8], b0r[8];
#pragma unroll
        for (int c = 0; c < 8; c++) { w0r[c] = w0[c]; b0r[c] = 65536.f * b0[c]; }
        for (int id = tid; id < 288; id += 128) {
            int j = id / 9, t = id % 9;
            float amin = 0.f, amax = 0.f, bs = 0.f;
#pragma unroll
            for (int c = 0; c < 8; c++) {
                float w = w1[j * 72 + c * 9 + t];
                if (w0r[c] >= 0.f) amin += w * w0r[c]; else amax += w * w0r[c];
                bs += w * b0r[c];
            }
            Amin[j][t] = amin; Amax[j][t] = amax; Bs[j][t] = bs;
            A2s[j][t]     = pk2(amin, amin);
            A2s[j][9 + t] = pk2(amax, amax);
        }
        if (tid < 32) {
            float wv = w2[tid];
            w2s[tid] = wv;
            w2p[tid] = pk2(wv, wv);
            b1s[tid] = b1[tid];
        }
        __syncthreads();
        if (tid < 32) {
            float cb = b1s[tid];
#pragma unroll
            for (int t = 0; t < 9; t++) cb += Bs[tid][t];
            cb2s[tid] = pk2(cb, cb);
        }
        __syncthreads();
    }

    const int img = blockIdx.z;
    const size_t ib = (size_t)img * NPIX;
    const float* gm = gmin + ib;
    const float* gx = gmax + ib;
    float* outp = out + ib;
    const float b2v = b2[0];

    if (blockIdx.x < 256) {
        const int tx = tid & 31, ty = tid >> 5;
        const int bx = blockIdx.x & 7, by = blockIdx.x >> 3;
        const int x0 = (bx * 32 + tx) * 2;
        const int y0 = (by * 4 + ty) * 4;
        const int xm2 = max(x0 - 2, 0);
        const int xp2 = min(x0 + 2, IMG - 2);

        unsigned long long tmin[6][3], tmax[6][3];
#pragma unroll
        for (int rr = 0; rr < 6; rr++) {
            int row = min(max(y0 + rr - 1, 0), IMG - 1);
            const float* pm = gm + (size_t)row * IMG;
            float2 L = *(const float2*)(pm + xm2);
            float2 Mv = *(const float2*)(pm + x0);
            float2 R = *(const float2*)(pm + xp2);
            tmin[rr][0] = pk2(L.y, Mv.x); tmin[rr][1] = pk2(Mv.x, Mv.y); tmin[rr][2] = pk2(Mv.y, R.x);
            const float* px = gx + (size_t)row * IMG;
            L = *(const float2*)(px + xm2);
            Mv = *(const float2*)(px + x0);
            R = *(const float2*)(px + xp2);
            tmax[rr][0] = pk2(L.y, Mv.x); tmax[rr][1] = pk2(Mv.x, Mv.y); tmax[rr][2] = pk2(Mv.y, R.x);
        }

        unsigned long long accp[4] = {0ULL, 0ULL, 0ULL, 0ULL};
#pragma unroll 2
        for (int j = 0; j < 32; j++) {
            unsigned long long u0 = cb2s[j], u1 = u0, u2 = u0, u3 = u0;
#pragma unroll
            for (int k = 0; k < 9; k++) {
                const int kh = k / 3, kw = k % 3;
                unsigned long long a = A2s[j][k];
                u0 = fma2(a, tmin[0 + kh][kw], u0);
                u1 = fma2(a, tmin[1 + kh][kw], u1);
                u2 = fma2(a, tmin[2 + kh][kw], u2);
                u3 = fma2(a, tmin[3 + kh][kw], u3);
            }
#pragma unroll
            for (int k = 0; k < 9; k++) {
                const int kh = k / 3, kw = k % 3;
                unsigned long long a = A2s[j][9 + k];
                u0 = fma2(a, tmax[0 + kh][kw], u0);
                u1 = fma2(a, tmax[1 + kh][kw], u1);
                u2 = fma2(a, tmax[2 + kh][kw], u2);
                u3 = fma2(a, tmax[3 + kh][kw], u3);
            }
            unsigned long long wp = w2p[j];
            float lo, hi;
            upk2(u0, lo, hi);
            accp[0] = fma2(wp, pk2(fmaxf(lo, 0.f), fmaxf(hi, 0.f)), accp[0]);
            upk2(u1, lo, hi);
            accp[1] = fma2(wp, pk2(fmaxf(lo, 0.f), fmaxf(hi, 0.f)), accp[1]);
            upk2(u2, lo, hi);
            accp[2] = fma2(wp, pk2(fmaxf(lo, 0.f), fmaxf(hi, 0.f)), accp[2]);
            upk2(u3, lo, hi);
            accp[3] = fma2(wp, pk2(fmaxf(lo, 0.f), fmaxf(hi, 0.f)), accp[3]);
        }

#pragma unroll
        for (int i = 0; i < 4; i++) {
            int yy = y0 + i;
            if (yy == 0 || yy == IMG - 1) continue;
            float ax, ay;
            upk2(accp[i], ax, ay);
            float ox = b2v + ax;
            float oy = b2v + ay;
            if (x0 == 0)              outp[(size_t)yy * IMG + 1] = oy;
            else if (x0 == IMG - 2)   outp[(size_t)yy * IMG + (IMG - 2)] = ox;
            else                      *(float2*)(outp + (size_t)yy * IMG + x0) = make_float2(ox, oy);
        }
    } else {
        const int bi = (blockIdx.x - 256) * 128 + tid;
        if (bi >= 2044) return;
        int x, y;
        if (bi < 512)        { y = 0;   x = bi; }
        else if (bi < 1024)  { y = 511; x = bi - 512; }
        else if (bi < 1534)  { x = 0;   y = bi - 1024 + 1; }
        else                 { x = 511; y = bi - 1534 + 1; }

        float vmn[9], vmx[9];
        bool valid[9];
#pragma unroll
        for (int k = 0; k < 9; k++) {
            int ty = y + k / 3 - 1, tx = x + k % 3 - 1;
            valid[k] = (ty >= 0 && ty < IMG && tx >= 0 && tx < IMG);
            size_t off = (size_t)min(max(ty, 0), IMG - 1) * IMG + (size_t)min(max(tx, 0), IMG - 1);
            vmn[k] = valid[k] ? gm[off] : 0.f;
            vmx[k] = valid[k] ? gx[off] : 0.f;
        }
        float acc = 0.f;
        for (int j = 0; j < 32; j++) {
            float u = b1s[j];
#pragma unroll
            for (int k = 0; k < 9; k++) {
                if (valid[k])
                    u += Amin[j][k] * vmn[k] + Amax[j][k] * vmx[k] + Bs[j][k];
            }
            acc = fmaf(w2s[j], fmaxf(u, 0.f), acc);
        }
        outp[(size_t)y * IMG + x] = b2v + acc;
    }
}

// ---------------------------------------------------------------------------
extern "C" void kernel_launch(void* const* d_in, const int* in_sizes, int n_in,
                              void* d_out, int out_size) {
    const float* x  = (const float*)d_in[0];
    const float* w0 = (const float*)d_in[1];
    const float* b0 = (const float*)d_in[2];
    const float* w1 = (const float*)d_in[3];
    const float* b1 = (const float*)d_in[4];
    const float* w2 = (const float*)d_in[5];
    const float* b2 = (const float*)d_in[6];
    float* out = (float*)d_out;

    static float *pMinA = nullptr, *pMinB = nullptr, *pMaxA = nullptr, *pMaxB = nullptr;
    if (!pMinA) {
        cudaGetSymbolAddress((void**)&pMinA, g_min_a);
        cudaGetSymbolAddress((void**)&pMinB, g_min_b);
        cudaGetSymbolAddress((void**)&pMaxA, g_max_a);
        cudaGetSymbolAddress((void**)&pMaxB, g_max_b);
    }

    dim3 rblk(128);
    dim3 rgrd(IMG / 8, NIMG, 2);
    round_kernel<<<rgrd, rblk>>>(x,     x,     pMinA, pMaxA);   // iters 1-4
    round_kernel<<<rgrd, rblk>>>(pMinA, pMaxA, pMinB, pMaxB);   // iters 5-8
    round_kernel<<<rgrd, rblk>>>(pMinB, pMaxB, pMinA, pMaxA);   // iters 9-12
    round_kernel<<<rgrd, rblk>>>(pMinA, pMaxA, pMinB, pMaxB);   // iters 13-16

    dim3 hgrd(272, 1, NIMG);
    head_kernel<<<hgrd, 128>>>(pMinB, pMaxB, w0, b0, w1, b1, w2, b2, out);
}